// round 8
// baseline (speedup 1.0000x reference)
#include <cuda_runtime.h>
#include <cuda_bf16.h>
#include <cstdint>

#define BATCH 4096
#define NST   512
#define IO    16
#define DS    32
#define PTOT  8192
#define NCH   32
#define LCH   16

typedef unsigned long long ull;

// ---------------- device scratch (static; no mallocs) ----------------
__device__ __align__(16) __nv_bfloat16 g_Uh[(size_t)BATCH * PTOT];
__device__ __align__(16) __nv_bfloat16 g_Ul[(size_t)BATCH * PTOT];
__device__ __align__(16) __nv_bfloat16 g_Th[(size_t)NCH * 256 * 320];  // T^T per chunk [n][k]
__device__ __align__(16) __nv_bfloat16 g_Tl[(size_t)NCH * 256 * 320];
__device__ __align__(16) __nv_bfloat16 g_Sh[(size_t)NCH * 64 * 256];   // S^T per chunk [n][k]
__device__ __align__(16) __nv_bfloat16 g_Sl[(size_t)NCH * 64 * 256];
__device__ __align__(16) float g_xloc[(size_t)BATCH * NCH * 64];       // [row][c][64]
__device__ __align__(16) __nv_bfloat16 g_xinh[(size_t)BATCH * NCH * 64];
__device__ __align__(16) __nv_bfloat16 g_xinl[(size_t)BATCH * NCH * 64];
__device__ float g_P2[2 * NCH * DS * DS];

// ---------------- f32x2 helpers ----------------
__device__ __forceinline__ ull pack2(float lo, float hi) {
    ull r; asm("mov.b64 %0, {%1, %2};" : "=l"(r) : "f"(lo), "f"(hi)); return r;
}
__device__ __forceinline__ ull dup2(float v) { return pack2(v, v); }
__device__ __forceinline__ void unpack2(ull p, float& lo, float& hi) {
    asm("mov.b64 {%0, %1}, %2;" : "=f"(lo), "=f"(hi) : "l"(p));
}
__device__ __forceinline__ ull fma2(ull a, ull b, ull c) {
    ull r; asm("fma.rn.f32x2 %0, %1, %2, %3;" : "=l"(r) : "l"(a), "l"(b), "l"(c)); return r;
}

// ---------------- cp.async helpers ----------------
__device__ __forceinline__ void cpasync16(void* s, const void* g) {
    uint32_t sa = (uint32_t)__cvta_generic_to_shared(s);
    asm volatile("cp.async.cg.shared.global [%0], [%1], 16;" :: "r"(sa), "l"(g));
}
__device__ __forceinline__ void cpcommit() { asm volatile("cp.async.commit_group;"); }
template<int N> __device__ __forceinline__ void cpwait() {
    asm volatile("cp.async.wait_group %0;" :: "n"(N));
}

// ---------------- mma.sync / ldmatrix helpers ----------------
__device__ __forceinline__ void ldmx4(uint32_t* r, uint32_t addr) {
    asm volatile("ldmatrix.sync.aligned.m8n8.x4.shared.b16 {%0,%1,%2,%3}, [%4];"
        : "=r"(r[0]), "=r"(r[1]), "=r"(r[2]), "=r"(r[3]) : "r"(addr));
}
__device__ __forceinline__ void ldmx2(uint32_t* r, uint32_t addr) {
    asm volatile("ldmatrix.sync.aligned.m8n8.x2.shared.b16 {%0,%1}, [%2];"
        : "=r"(r[0]), "=r"(r[1]) : "r"(addr));
}
__device__ __forceinline__ void mma16816(float* c, const uint32_t* a, const uint32_t* b) {
    asm volatile(
        "mma.sync.aligned.m16n8k16.row.col.f32.bf16.bf16.f32 "
        "{%0,%1,%2,%3}, {%4,%5,%6,%7}, {%8,%9}, {%0,%1,%2,%3};"
        : "+f"(c[0]), "+f"(c[1]), "+f"(c[2]), "+f"(c[3])
        : "r"(a[0]), "r"(a[1]), "r"(a[2]), "r"(a[3]), "r"(b[0]), "r"(b[1]));
}
// 64B-row tile swizzle: logical (row r, 16B chunk c in 0..3)
__device__ __forceinline__ uint32_t swz32(int r, int c) {
    return (uint32_t)(r * 64 + (((c ^ (r >> 1)) & 3) << 4));
}

__device__ __forceinline__ void split_bf16(float v, __nv_bfloat16& h, __nv_bfloat16& l) {
    h = __float2bfloat16(v);
    l = __float2bfloat16(v - __bfloat162float(h));
}

// =====================================================================
// 1. Split U -> Uh, Ul
// =====================================================================
__global__ __launch_bounds__(256)
void convertU_kernel(const float* __restrict__ U) {
    const size_t i = (size_t)blockIdx.x * 256 + threadIdx.x;
    const float4 v = ((const float4*)U)[i];
    __nv_bfloat16 h0, h1, h2, h3, l0, l1, l2, l3;
    split_bf16(v.x, h0, l0); split_bf16(v.y, h1, l1);
    split_bf16(v.z, h2, l2); split_bf16(v.w, h3, l3);
    ((__nv_bfloat162*)g_Uh)[2*i]   = __nv_bfloat162(h0, h1);
    ((__nv_bfloat162*)g_Uh)[2*i+1] = __nv_bfloat162(h2, h3);
    ((__nv_bfloat162*)g_Ul)[2*i]   = __nv_bfloat162(l0, l1);
    ((__nv_bfloat162*)g_Ul)[2*i+1] = __nv_bfloat162(l2, l3);
}

// =====================================================================
// 2. Strip precompute -> T^T (bf16 h/l) input blocks + S^T columns
// =====================================================================
__global__ __launch_bounds__(128)
void strip_kernel(const float* __restrict__ A, const float* __restrict__ B,
                  const float* __restrict__ C, const float* __restrict__ D,
                  const float* __restrict__ E, const float* __restrict__ F,
                  const float* __restrict__ G) {
    __shared__ float sV[2][DS][IO];
    __shared__ float sW2[DS][DS];
    __shared__ float sW1[IO][DS];
    const int tid = threadIdx.x;
    const int c = blockIdx.x, s = blockIdx.y, d = blockIdx.z;
    const int k0 = c * LCH;
    __nv_bfloat16* Th = g_Th + (size_t)c * 256 * 320;
    __nv_bfloat16* Tl = g_Tl + (size_t)c * 256 * 320;

    const float* src0 = ((d == 0) ? B : F) + (size_t)(k0 + s) * 512;
    for (int e = tid; e < 512; e += 128) sV[0][e >> 4][e & 15] = src0[e];
    if (d == 0) {
        const float* Ds = D + (size_t)(k0 + s) * 256;
        for (int e = tid; e < 256; e += 128) {
            const int o = e >> 4, i = e & 15;
            __nv_bfloat16 h, l; split_bf16(Ds[o * 16 + i], h, l);
            const size_t idx = (size_t)(s * 16 + o) * 320 + s * 16 + i;
            Th[idx] = h; Tl[idx] = l;
        }
    }
    __syncthreads();

    int pb = 0;
    const int nsteps = (d == 0) ? (LCH - 1 - s) : s;
    for (int step = 0; step < nsteps; ++step) {
        const int t = (d == 0) ? (s + 1 + step) : (s - 1 - step);
        const int k = k0 + t;
        const float* W2 = ((d == 0) ? A : E) + (size_t)k * 1024;
        const float* W1 = ((d == 0) ? C : G) + (size_t)k * 512;
        for (int e = tid; e < 1024; e += 128) sW2[e >> 5][e & 31] = W2[e];
        for (int e = tid; e < 512;  e += 128) sW1[e >> 5][e & 31] = W1[e];
        __syncthreads();
        for (int e = tid; e < 256; e += 128) {
            const int o = e >> 4, i = e & 15;
            float acc = 0.f;
#pragma unroll
            for (int l = 0; l < DS; ++l) acc += sW1[o][l] * sV[pb][l][i];
            __nv_bfloat16 h, l2; split_bf16(acc, h, l2);
            const size_t idx = (size_t)(t * 16 + o) * 320 + s * 16 + i;
            Th[idx] = h; Tl[idx] = l2;
        }
        for (int e = tid; e < 512; e += 128) {
            const int j = e >> 4, i = e & 15;
            float acc = 0.f;
#pragma unroll
            for (int l = 0; l < DS; ++l) acc += sW2[j][l] * sV[pb][l][i];
            sV[pb ^ 1][j][i] = acc;
        }
        __syncthreads();
        pb ^= 1;
    }
    for (int e = tid; e < 512; e += 128) {
        const int j = e >> 4, i = e & 15;
        __nv_bfloat16 h, l; split_bf16(sV[pb][j][i], h, l);
        const size_t idx = (size_t)c * 64 * 256 + (size_t)(d * 32 + j) * 256 + s * 16 + i;
        g_Sh[idx] = h; g_Sl[idx] = l;
    }
}

// =====================================================================
// 3. M/N correction rows of T^T + propagators
// =====================================================================
__global__ __launch_bounds__(256)
void mn_kernel(const float* __restrict__ A, const float* __restrict__ C,
               const float* __restrict__ E, const float* __restrict__ G) {
    __shared__ float sV[2][DS][DS];
    __shared__ float sW2[DS][DS];
    __shared__ float sW1[IO][DS];
    const int tid = threadIdx.x;
    const int c = blockIdx.x, d = blockIdx.y;
    const int k0 = c * LCH;
    __nv_bfloat16* Th = g_Th + (size_t)c * 256 * 320;
    __nv_bfloat16* Tl = g_Tl + (size_t)c * 256 * 320;

    for (int e = tid; e < 1024; e += 256)
        sV[0][e >> 5][e & 31] = ((e >> 5) == (e & 31)) ? 1.f : 0.f;
    __syncthreads();

    int pb = 0;
    for (int step = 0; step < LCH; ++step) {
        const int t = (d == 0) ? step : (LCH - 1 - step);
        const int k = k0 + t;
        const float* W2 = ((d == 0) ? A : E) + (size_t)k * 1024;
        const float* W1 = ((d == 0) ? C : G) + (size_t)k * 512;
        for (int e = tid; e < 1024; e += 256) sW2[e >> 5][e & 31] = W2[e];
        for (int e = tid; e < 512;  e += 256) sW1[e >> 5][e & 31] = W1[e];
        __syncthreads();
        for (int e = tid; e < 512; e += 256) {
            const int o = e >> 5, j = e & 31;
            float acc = 0.f;
#pragma unroll
            for (int l = 0; l < DS; ++l) acc += sW1[o][l] * sV[pb][l][j];
            __nv_bfloat16 h, l2; split_bf16(acc, h, l2);
            const size_t idx = (size_t)(t * 16 + o) * 320 + 256 + d * 32 + j;
            Th[idx] = h; Tl[idx] = l2;
        }
        for (int e = tid; e < 1024; e += 256) {
            const int i = e >> 5, j = e & 31;
            float acc = 0.f;
#pragma unroll
            for (int l = 0; l < DS; ++l) acc += sW2[i][l] * sV[pb][l][j];
            sV[pb ^ 1][i][j] = acc;
        }
        __syncthreads();
        pb ^= 1;
    }
    for (int e = tid; e < 1024; e += 256) {
        const int i = e >> 5, j = e & 31;
        g_P2[(size_t)(d * NCH + c) * 1024 + j * 32 + i] = sV[pb][i][j];
    }
}

// =====================================================================
// 4. GEMM1 (mma.sync): xloc[128x64] = A[128x256] x S^T, split-bf16
//    k-chunk 32; stage 24KB = Ah 8K | Al 8K | Bh 4K | Bl 4K; 4 stages (96KB)
//    128 thr = 4 warps (2m x 2n), warp tile 64x32. 8 k-chunks.
// =====================================================================
#define G1_STAGE 24576
__global__ __launch_bounds__(128)
void gemm1_kernel() {
    extern __shared__ char smem[];
    const uint32_t sb = (uint32_t)__cvta_generic_to_shared(smem);
    const int tid = threadIdx.x, wid = tid >> 5, lane = tid & 31;
    const int mt = blockIdx.x, c = blockIdx.y;
    const int row0 = mt * 128;
    const int wm = wid & 1, wn = wid >> 1;
    const int mbase = wm * 64, nbase = wn * 32;

    auto load_stage = [&](int st, int kt) {
        char* base = smem + st * G1_STAGE;
#pragma unroll
        for (int q = 0; q < 4; ++q) {
            const int i = tid + 128 * q, r = i >> 2, ch = i & 3;
            const uint32_t o = swz32(r, ch);
            const size_t g = (size_t)(row0 + r) * PTOT + c * 256 + kt * 32 + ch * 8;
            cpasync16(base + o, g_Uh + g);
            cpasync16(base + 8192 + o, g_Ul + g);
        }
#pragma unroll
        for (int q = 0; q < 2; ++q) {
            const int i = tid + 128 * q, r = i >> 2, ch = i & 3;
            const uint32_t o = swz32(r, ch);
            const size_t g = (size_t)c * 64 * 256 + (size_t)r * 256 + kt * 32 + ch * 8;
            cpasync16(base + 16384 + o, g_Sh + g);
            cpasync16(base + 20480 + o, g_Sl + g);
        }
    };

    float acc[4][4][4];
#pragma unroll
    for (int mi = 0; mi < 4; ++mi)
#pragma unroll
        for (int ni = 0; ni < 4; ++ni)
#pragma unroll
            for (int q = 0; q < 4; ++q) acc[mi][ni][q] = 0.f;

    load_stage(0, 0); cpcommit();
    load_stage(1, 1); cpcommit();
    load_stage(2, 2); cpcommit();

    const int atile = lane >> 3;
    const int ar_off = (lane & 7) + (atile & 1) * 8;
    const int ak_off = atile >> 1;
    const int btt = lane & 15;
    const int br_off = btt & 7;
    const int bk_off = btt >> 3;

#pragma unroll 1
    for (int kt = 0; kt < 8; ++kt) {
        const int st = kt & 3;
        cpwait<2>(); __syncthreads();
        const uint32_t tb = sb + st * G1_STAGE;
#pragma unroll
        for (int ks = 0; ks < 2; ++ks) {
            uint32_t bh[4][2], bl[4][2];
#pragma unroll
            for (int ni = 0; ni < 4; ++ni) {
                const int r = nbase + ni * 8 + br_off;
                const uint32_t o = swz32(r, 2 * ks + bk_off);
                ldmx2(bh[ni], tb + 16384 + o);
                ldmx2(bl[ni], tb + 20480 + o);
            }
#pragma unroll
            for (int mi = 0; mi < 4; ++mi) {
                const int r = mbase + mi * 16 + ar_off;
                const uint32_t o = swz32(r, 2 * ks + ak_off);
                uint32_t ah[4], al[4];
                ldmx4(ah, tb + o);
                ldmx4(al, tb + 8192 + o);
#pragma unroll
                for (int ni = 0; ni < 4; ++ni) {
                    mma16816(acc[mi][ni], ah, bh[ni]);
                    mma16816(acc[mi][ni], ah, bl[ni]);
                    mma16816(acc[mi][ni], al, bh[ni]);
                }
            }
        }
        if (kt + 3 < 8) load_stage((kt + 3) & 3, kt + 3);
        cpcommit();
    }

    // epilogue -> g_xloc [row][c][64]
#pragma unroll
    for (int mi = 0; mi < 4; ++mi) {
        const int r0 = row0 + mbase + mi * 16 + (lane >> 2);
#pragma unroll
        for (int ni = 0; ni < 4; ++ni) {
            const int n = nbase + ni * 8 + (lane & 3) * 2;
            float* d0 = g_xloc + ((size_t)r0 * NCH + c) * 64 + n;
            float* d1 = g_xloc + ((size_t)(r0 + 8) * NCH + c) * 64 + n;
            *(float2*)d0 = make_float2(acc[mi][ni][0], acc[mi][ni][1]);
            *(float2*)d1 = make_float2(acc[mi][ni][2], acc[mi][ni][3]);
        }
    }
}

// =====================================================================
// 5. Phase B: chunk recombination, one thread per row; emits xin bf16 h/l
// =====================================================================
__global__ __launch_bounds__(64)
void phaseB_kernel() {
    __shared__ float sP[DS * DS];
    const int tid = threadIdx.x;
    const int d = blockIdx.y;
    const int row = blockIdx.x * 64 + tid;

    ull xp[16];
#pragma unroll
    for (int ip = 0; ip < 16; ++ip) xp[ip] = 0;

#pragma unroll 1
    for (int ci = 0; ci < NCH; ++ci) {
        const int c = d ? (NCH - 1 - ci) : ci;
        __syncthreads();
        {
            const float4* src = (const float4*)(g_P2 + (size_t)(d * NCH + c) * 1024);
#pragma unroll
            for (int q = 0; q < 4; ++q) ((float4*)sP)[tid + 64 * q] = src[tid + 64 * q];
        }
        __syncthreads();

        float x[DS];
        const size_t xoff = ((size_t)row * NCH + c) * 64 + d * 32;
#pragma unroll
        for (int ip = 0; ip < 16; ++ip) {
            unpack2(xp[ip], x[2 * ip], x[2 * ip + 1]);
            __nv_bfloat16 h0, l0, h1, l1;
            split_bf16(x[2 * ip], h0, l0);
            split_bf16(x[2 * ip + 1], h1, l1);
            ((__nv_bfloat162*)(g_xinh + xoff))[ip] = __nv_bfloat162(h0, h1);
            ((__nv_bfloat162*)(g_xinl + xoff))[ip] = __nv_bfloat162(l0, l1);
        }

        ull acc[16];
        {
            const float4* xl = (const float4*)(g_xloc + xoff);
#pragma unroll
            for (int q = 0; q < 8; ++q) {
                float4 v = xl[q];
                acc[2 * q]     = pack2(v.x, v.y);
                acc[2 * q + 1] = pack2(v.z, v.w);
            }
        }
#pragma unroll
        for (int j = 0; j < DS; ++j) {
            const ull xx = dup2(x[j]);
            const ulonglong2* pr = (const ulonglong2*)&sP[j * DS];
#pragma unroll
            for (int t = 0; t < 8; ++t) {
                const ulonglong2 pv = pr[t];
                acc[2 * t]     = fma2(pv.x, xx, acc[2 * t]);
                acc[2 * t + 1] = fma2(pv.y, xx, acc[2 * t + 1]);
            }
        }
#pragma unroll
        for (int ip = 0; ip < 16; ++ip) xp[ip] = acc[ip];
    }
}

// =====================================================================
// 6. GEMM2 (mma.sync): out[128x128] = A[128x320] x T^T + bias, split-bf16
//    k-chunk 32; stage 32KB = Ah 8K | Al 8K | Bh 8K | Bl 8K; 6 stages (192KB)
//    256 thr = 8 warps (2m x 4n), warp tile 64x32. 10 k-chunks.
// =====================================================================
#define G2_STAGE 32768
__global__ __launch_bounds__(256)
void gemm2_kernel(const float* __restrict__ bias, float* __restrict__ out) {
    extern __shared__ char smem[];
    const uint32_t sb = (uint32_t)__cvta_generic_to_shared(smem);
    const int tid = threadIdx.x, wid = tid >> 5, lane = tid & 31;
    const int mt = blockIdx.x, nt = blockIdx.y, c = blockIdx.z;
    const int row0 = mt * 128, nc = nt * 128;
    const int wm = wid & 1, wn = wid >> 1;
    const int mbase = wm * 64, nbase = wn * 32;

    auto load_stage = [&](int st, int kt) {
        char* base = smem + st * G2_STAGE;
#pragma unroll
        for (int q = 0; q < 2; ++q) {
            const int i = tid + 256 * q, r = i >> 2, ch = i & 3;
            const uint32_t o = swz32(r, ch);
            const __nv_bfloat16 *sh, *sl;
            if (kt < 8) {
                const size_t g = (size_t)(row0 + r) * PTOT + c * 256 + kt * 32 + ch * 8;
                sh = g_Uh + g; sl = g_Ul + g;
            } else {
                const size_t g = ((size_t)(row0 + r) * NCH + c) * 64 + (kt - 8) * 32 + ch * 8;
                sh = g_xinh + g; sl = g_xinl + g;
            }
            cpasync16(base + o, sh);
            cpasync16(base + 8192 + o, sl);
        }
#pragma unroll
        for (int q = 0; q < 2; ++q) {
            const int i = tid + 256 * q, r = i >> 2, ch = i & 3;
            const uint32_t o = swz32(r, ch);
            const size_t g = (size_t)c * 256 * 320 + (size_t)(nc + r) * 320 + kt * 32 + ch * 8;
            cpasync16(base + 16384 + o, g_Th + g);
            cpasync16(base + 24576 + o, g_Tl + g);
        }
    };

    float acc[4][4][4];
#pragma unroll
    for (int mi = 0; mi < 4; ++mi)
#pragma unroll
        for (int ni = 0; ni < 4; ++ni)
#pragma unroll
            for (int q = 0; q < 4; ++q) acc[mi][ni][q] = 0.f;

    load_stage(0, 0); cpcommit();
    load_stage(1, 1); cpcommit();
    load_stage(2, 2); cpcommit();
    load_stage(3, 3); cpcommit();
    load_stage(4, 4); cpcommit();

    const int atile = lane >> 3;
    const int ar_off = (lane & 7) + (atile & 1) * 8;
    const int ak_off = atile >> 1;
    const int btt = lane & 15;
    const int br_off = btt & 7;
    const int bk_off = btt >> 3;

#pragma unroll 1
    for (int kt = 0; kt < 10; ++kt) {
        const int st = kt % 6;
        cpwait<4>(); __syncthreads();
        const uint32_t tb = sb + st * G2_STAGE;
#pragma unroll
        for (int ks = 0; ks < 2; ++ks) {
            uint32_t bh[4][2], bl[4][2];
#pragma unroll
            for (int ni = 0; ni < 4; ++ni) {
                const int r = nbase + ni * 8 + br_off;
                const uint32_t o = swz32(r, 2 * ks + bk_off);
                ldmx2(bh[ni], tb + 16384 + o);
                ldmx2(bl[ni], tb + 24576 + o);
            }
#pragma unroll
            for (int mi = 0; mi < 4; ++mi) {
                const int r = mbase + mi * 16 + ar_off;
                const uint32_t o = swz32(r, 2 * ks + ak_off);
                uint32_t ah[4], al[4];
                ldmx4(ah, tb + o);
                ldmx4(al, tb + 8192 + o);
#pragma unroll
                for (int ni = 0; ni < 4; ++ni) {
                    mma16816(acc[mi][ni], ah, bh[ni]);
                    mma16816(acc[mi][ni], ah, bl[ni]);
                    mma16816(acc[mi][ni], al, bh[ni]);
                }
            }
        }
        if (kt + 5 < 10) load_stage((kt + 5) % 6, kt + 5);
        cpcommit();
    }

    // epilogue: + bias, store float2 per tile-row
#pragma unroll
    for (int mi = 0; mi < 4; ++mi) {
        const int r0 = row0 + mbase + mi * 16 + (lane >> 2);
#pragma unroll
        for (int ni = 0; ni < 4; ++ni) {
            const int n = nc + nbase + ni * 8 + (lane & 3) * 2;
            const float2 bv = *(const float2*)(bias + c * 256 + n);
            float* d0 = out + (size_t)r0 * PTOT + c * 256 + n;
            float* d1 = out + (size_t)(r0 + 8) * PTOT + c * 256 + n;
            *(float2*)d0 = make_float2(acc[mi][ni][0] + bv.x, acc[mi][ni][1] + bv.y);
            *(float2*)d1 = make_float2(acc[mi][ni][2] + bv.x, acc[mi][ni][3] + bv.y);
        }
    }
}

// =====================================================================
extern "C" void kernel_launch(void* const* d_in, const int* in_sizes, int n_in,
                              void* d_out, int out_size) {
    const float* U    = (const float*)d_in[0];
    const float* A    = (const float*)d_in[1];
    const float* B    = (const float*)d_in[2];
    const float* C    = (const float*)d_in[3];
    const float* D    = (const float*)d_in[4];
    const float* E    = (const float*)d_in[5];
    const float* F    = (const float*)d_in[6];
    const float* G    = (const float*)d_in[7];
    const float* bias = (const float*)d_in[8];
    float* out = (float*)d_out;

    cudaFuncSetAttribute(gemm1_kernel, cudaFuncAttributeMaxDynamicSharedMemorySize, 4 * G1_STAGE);
    cudaFuncSetAttribute(gemm2_kernel, cudaFuncAttributeMaxDynamicSharedMemorySize, 6 * G2_STAGE);

    convertU_kernel<<<(BATCH * PTOT / 4) / 256, 256>>>(U);
    strip_kernel<<<dim3(NCH, LCH, 2), 128>>>(A, B, C, D, E, F, G);
    mn_kernel<<<dim3(NCH, 2), 256>>>(A, C, E, G);
    gemm1_kernel<<<dim3(BATCH / 128, NCH), 128, 4 * G1_STAGE>>>();
    phaseB_kernel<<<dim3(BATCH / 64, 2), 64>>>();
    gemm2_kernel<<<dim3(BATCH / 128, 2, NCH), 256, 6 * G2_STAGE>>>(bias, out);
}